// round 2
// baseline (speedup 1.0000x reference)
#include <cuda_runtime.h>

#define T_STEPS 128
#define H       20
#define H3      60
#define NB      2048
#define LOUT    15
#define EPB     16       // batch elements per block
#define THREADS 128      // 8 threads per element, 4 warps per block
#define WROW    96       // padded weight row: 3 gates * 8 slots * 4 floats
#define HSTRIDE 25       // u64 stride per element h-vector (20 + pad, conflict-free)

typedef unsigned long long u64;

// padded, bias-folded W0 gather table: [V=256][96]
__device__ float W0pad[256 * WROW];

__device__ __forceinline__ u64 pack2(float a, float b) {
    u64 r; asm("mov.b64 %0,{%1,%2};" : "=l"(r) : "f"(a), "f"(b)); return r;
}
__device__ __forceinline__ u64 ffma2(u64 a, u64 b, u64 c) {
    u64 d; asm("fma.rn.f32x2 %0,%1,%2,%3;" : "=l"(d) : "l"(a), "l"(b), "l"(c)); return d;
}
__device__ __forceinline__ void unp(u64 p, float& lo, float& hi) {
    asm("mov.b64 {%0,%1},%2;" : "=f"(lo), "=f"(hi) : "l"(p));
}
__device__ __forceinline__ float sigm(float x) {
    float e = __expf(-x);
    return __fdividef(1.f, 1.f + e);
}
__device__ __forceinline__ float tanh_f(float x) {
    x = fminf(fmaxf(x, -30.f), 30.f);
    float e = __expf(-2.f * x);
    return __fdividef(1.f - e, 1.f + e);
}

// prep: W0pad[v][g*32 + s*4 + i] = (i<3 && 3s+i<20) ? W0[v][g*20+3s+i] + b0i[g*20+3s+i] : 0
__global__ void prep_w0(const float* __restrict__ W0, const float* __restrict__ b0i) {
    int idx = blockIdx.x * 256 + threadIdx.x;           // 24576 total
    int v = idx / WROW, rem = idx - v * WROW;
    int g = rem >> 5, t = rem & 31, s = t >> 2, ii = t & 3;
    int c = 3 * s + ii;
    float val = 0.f;
    if (ii < 3 && c < H) val = W0[v * H3 + g * H + c] + b0i[g * H + c];
    W0pad[idx] = val;
}

// matvec over 20 h-rows; acc pre-initialized with bias. M rows are WROW floats,
// thread's 16B slot at offset soff (= (g*8+s)*16 bytes handled via g*32+s*4 floats).
__device__ __forceinline__ void matvec(const float* __restrict__ M,
                                       const u64* __restrict__ hb,
                                       int s4, u64 acc[6]) {
#pragma unroll
    for (int k = 0; k < H; k++) {
        u64 h2 = hb[k];
        const float* row = M + k * WROW + s4;
#pragma unroll
        for (int g = 0; g < 3; g++) {
            ulonglong2 q = *reinterpret_cast<const ulonglong2*>(row + g * 32);
            acc[2 * g]     = ffma2(h2, q.x, acc[2 * g]);
            acc[2 * g + 1] = ffma2(h2, q.y, acc[2 * g + 1]);
        }
    }
}

__device__ __forceinline__ void unp3(const u64 acc[6], int g, float o[3]) {
    float hi_pad;
    unp(acc[2 * g], o[0], o[1]);
    unp(acc[2 * g + 1], o[2], hi_pad);
}

__global__ void __launch_bounds__(THREADS)
gru2_kernel(const int* __restrict__ x,
            const float* __restrict__ U0, const float* __restrict__ b0r,
            const float* __restrict__ W1, const float* __restrict__ U1,
            const float* __restrict__ b1i, const float* __restrict__ b1r,
            const float* __restrict__ Wd, const float* __restrict__ bd,
            float* __restrict__ out)
{
    __shared__ __align__(16) float U0x[H * WROW];
    __shared__ __align__(16) float W1x[H * WROW];
    __shared__ __align__(16) float U1x[H * WROW];
    __shared__ float Wdx[H * LOUT + LOUT];
    __shared__ int   xs[EPB * T_STEPS];
    __shared__ u64   hs0[2][EPB][HSTRIDE];
    __shared__ u64   hs1[2][EPB][HSTRIDE];

    const int tid = threadIdx.x;

    // stage weights into padded SMEM layout
    for (int i = tid; i < H * WROW; i += THREADS) {
        int k = i / WROW, rem = i - k * WROW;
        int g = rem >> 5, t = rem & 31, sl = t >> 2, ii = t & 3;
        int c = 3 * sl + ii;
        bool ok = (ii < 3 && c < H);
        int src = k * H3 + g * H + c;
        U0x[i] = ok ? U0[src] : 0.f;
        W1x[i] = ok ? W1[src] : 0.f;
        U1x[i] = ok ? U1[src] : 0.f;
    }
    for (int i = tid; i < H * LOUT; i += THREADS) Wdx[i] = Wd[i];
    for (int i = tid; i < LOUT; i += THREADS)     Wdx[H * LOUT + i] = bd[i];
    for (int i = tid; i < EPB * T_STEPS; i += THREADS)
        xs[i] = x[blockIdx.x * EPB * T_STEPS + i];
    for (int i = tid; i < 2 * EPB * HSTRIDE; i += THREADS) {
        (&hs0[0][0][0])[i] = 0ull;
        (&hs1[0][0][0])[i] = 0ull;
    }
    __syncthreads();

    const int lane = tid & 31, wid = tid >> 5;
    const int e  = wid * 4 + (lane >> 3);   // element within block (0..15)
    const int s  = lane & 7;                // slot within element (0..7)
    const int s4 = s * 4;
    const int c0 = 3 * s;                   // first owned h-lane

    // per-thread bias pairs (accumulator init): [matrix][gate][lo/hi]
    u64 bU0[6], bW1[6], bU1[6];
    {
        auto ld3 = [&](const float* bv, u64* dst) {
#pragma unroll
            for (int g = 0; g < 3; g++) {
                float f0 = (c0 < H)     ? bv[g * H + c0]     : 0.f;
                float f1 = (c0 + 1 < H) ? bv[g * H + c0 + 1] : 0.f;
                float f2 = (c0 + 2 < H) ? bv[g * H + c0 + 2] : 0.f;
                dst[2 * g]     = pack2(f0, f1);
                dst[2 * g + 1] = pack2(f2, 0.f);
            }
        };
        ld3(b0r, bU0);
        ld3(b1i, bW1);
        ld3(b1r, bU1);
    }

    float ho0[3] = {0, 0, 0}, ho1[3] = {0, 0, 0};
    const int* xrow = &xs[(e) * T_STEPS];

    for (int t = 0; t < T_STEPS; t++) {
        const int cur = t & 1, nxt = cur ^ 1;

        // xw0 gather (b0i pre-folded into W0pad)
        const float4* w0p = reinterpret_cast<const float4*>(W0pad + xrow[t] * WROW);
        float4 qz = w0p[s], qr = w0p[8 + s], qh = w0p[16 + s];
        float xz[3] = {qz.x, qz.y, qz.z};
        float xr[3] = {qr.x, qr.y, qr.z};
        float xh[3] = {qh.x, qh.y, qh.z};

        // rec0 = h0 @ U0 + b0r
        u64 a0[6];
#pragma unroll
        for (int i = 0; i < 6; i++) a0[i] = bU0[i];
        matvec(U0x, hs0[cur][e], s4, a0);

        // rec1 = h1 @ U1 + b1r (independent of h0 publish)
        u64 a1[6];
#pragma unroll
        for (int i = 0; i < 6; i++) a1[i] = bU1[i];
        matvec(U1x, hs1[cur][e], s4, a1);

        // layer-0 gates for owned lanes
        {
            float rz[3], rr[3], rh[3];
            unp3(a0, 0, rz); unp3(a0, 1, rr); unp3(a0, 2, rh);
#pragma unroll
            for (int j = 0; j < 3; j++) {
                float z  = sigm(xz[j] + rz[j]);
                float rg = sigm(xr[j] + rr[j]);
                float hh = tanh_f(xh[j] + rg * rh[j]);
                ho0[j] = z * (ho0[j] - hh) + hh;
            }
        }
        // publish h0 (duplicated pairs)
#pragma unroll
        for (int j = 0; j < 3; j++)
            if (c0 + j < H) hs0[nxt][e][c0 + j] = pack2(ho0[j], ho0[j]);
        __syncwarp();

        // xw1 = h0_new @ W1 + b1i
        u64 a2[6];
#pragma unroll
        for (int i = 0; i < 6; i++) a2[i] = bW1[i];
        matvec(W1x, hs0[nxt][e], s4, a2);

        // layer-1 gates
        {
            float xz1[3], xr1[3], xh1[3], rz1[3], rr1[3], rh1[3];
            unp3(a2, 0, xz1); unp3(a2, 1, xr1); unp3(a2, 2, xh1);
            unp3(a1, 0, rz1); unp3(a1, 1, rr1); unp3(a1, 2, rh1);
#pragma unroll
            for (int j = 0; j < 3; j++) {
                float z  = sigm(xz1[j] + rz1[j]);
                float rg = sigm(xr1[j] + rr1[j]);
                float hh = tanh_f(xh1[j] + rg * rh1[j]);
                ho1[j] = z * (ho1[j] - hh) + hh;
            }
        }
#pragma unroll
        for (int j = 0; j < 3; j++)
            if (c0 + j < H) hs1[nxt][e][c0 + j] = pack2(ho1[j], ho1[j]);
        __syncwarp();
    }

    // logits = softmax(h1 @ Wd + bd); final h1 in buffer 0 (T even)
    const u64* h1f = hs1[0][e];
    float lg[LOUT];
#pragma unroll
    for (int c = 0; c < LOUT; c++) lg[c] = Wdx[H * LOUT + c];
#pragma unroll
    for (int k = 0; k < H; k++) {
        float hk, dummy; unp(h1f[k], hk, dummy);
#pragma unroll
        for (int c = 0; c < LOUT; c++) lg[c] = fmaf(hk, Wdx[k * LOUT + c], lg[c]);
    }
    float m = lg[0];
#pragma unroll
    for (int c = 1; c < LOUT; c++) m = fmaxf(m, lg[c]);
    float p[LOUT], sum = 0.f;
#pragma unroll
    for (int c = 0; c < LOUT; c++) { p[c] = __expf(lg[c] - m); sum += p[c]; }
    float inv = __fdividef(1.f, sum);

    const int b = blockIdx.x * EPB + e;
#pragma unroll
    for (int c = s; c < LOUT; c += 8)
        out[b * LOUT + c] = p[c] * inv;
}

extern "C" void kernel_launch(void* const* d_in, const int* in_sizes, int n_in,
                              void* d_out, int out_size) {
    const int*   x   = (const int*)d_in[0];
    const float* W0  = (const float*)d_in[1];
    const float* U0  = (const float*)d_in[2];
    const float* b0i = (const float*)d_in[3];
    const float* b0r = (const float*)d_in[4];
    const float* W1  = (const float*)d_in[5];
    const float* U1  = (const float*)d_in[6];
    const float* b1i = (const float*)d_in[7];
    const float* b1r = (const float*)d_in[8];
    const float* Wd  = (const float*)d_in[9];
    const float* bd  = (const float*)d_in[10];
    // d_in[11] = drop_rate (identity), unused

    prep_w0<<<(256 * WROW) / 256, 256>>>(W0, b0i);
    gru2_kernel<<<NB / EPB, THREADS>>>(x, U0, b0r, W1, U1, b1i, b1r, Wd, bd,
                                       (float*)d_out);
}

// round 3
// speedup vs baseline: 2.3623x; 2.3623x over previous
#include <cuda_runtime.h>
#include <math_constants.h>

#define H        20
#define H3       60
#define NB       2048
#define LOUT     15
#define TSTEPS   128
#define WPAD     64      // padded W0 row (floats)

typedef unsigned long long u64;

// bias-folded, lane-interleaved W0 gather table: [V=256][64]
// slot 2l = col l, slot 2l+1 = col 30+l (l<30); slots 60..63 = 0
__device__ float W0pad[256 * WPAD];

__device__ __forceinline__ u64 pack2(float a, float b) {
    u64 r; asm("mov.b64 %0,{%1,%2};" : "=l"(r) : "f"(a), "f"(b)); return r;
}
__device__ __forceinline__ u64 ffma2(u64 a, u64 b, u64 c) {
    u64 d; asm("fma.rn.f32x2 %0,%1,%2,%3;" : "=l"(d) : "l"(a), "l"(b), "l"(c)); return d;
}
__device__ __forceinline__ void unp(u64 p, float& lo, float& hi) {
    asm("mov.b64 {%0,%1},%2;" : "=f"(lo), "=f"(hi) : "l"(p));
}
__device__ __forceinline__ float tanh_fast(float x) {
    float y; asm("tanh.approx.f32 %0,%1;" : "=f"(y) : "f"(x)); return y;
}
__device__ __forceinline__ float sigm_fast(float x) {   // 0.5 + 0.5*tanh(x/2)
    return fmaf(0.5f, tanh_fast(0.5f * x), 0.5f);
}

__global__ void prep_w0(const float* __restrict__ W0, const float* __restrict__ b0i) {
    int idx = blockIdx.x * 256 + threadIdx.x;      // 16384 = 256*64
    int v = idx >> 6, sl = idx & 63;
    int l = sl >> 1;
    int c = (sl & 1) ? 30 + l : l;
    float val = 0.f;
    if (l < 30) val = W0[v * H3 + c] + b0i[c];
    W0pad[idx] = val;
}

// acc over k-pairs: lanes of the f32x2 hold (even-k sum, odd-k sum)
__device__ __forceinline__ void matvec(const u64 wa[10], const u64 wb[10],
                                       u64 biasA, u64 biasB, const u64 hp[10],
                                       float& r1, float& r2) {
    u64 aA = biasA, aB = biasB;
#pragma unroll
    for (int m = 0; m < 10; m++) {
        aA = ffma2(hp[m], wa[m], aA);
        aB = ffma2(hp[m], wb[m], aB);
    }
    float lo, hi;
    unp(aA, lo, hi); r1 = lo + hi;
    unp(aB, lo, hi); r2 = lo + hi;
}

__global__ void __launch_bounds__(128, 1)
gru2_kernel(const int* __restrict__ x,
            const float* __restrict__ U0, const float* __restrict__ b0r,
            const float* __restrict__ W1, const float* __restrict__ U1,
            const float* __restrict__ b1i, const float* __restrict__ b1r,
            const float* __restrict__ Wd, const float* __restrict__ bd,
            float* __restrict__ out)
{
    const unsigned F = 0xFFFFFFFFu;
    const int lane = threadIdx.x & 31;
    const int b = blockIdx.x * 4 + (threadIdx.x >> 5);   // element (grid 512 x 4 warps)
    const bool act = lane < 30;
    const int c1 = lane, c2 = 30 + lane;

    // ---- weights into registers: k-pair packed, cols c1/c2, 3 matrices ----
    u64 wU0a[10], wU0b[10], wW1a[10], wW1b[10], wU1a[10], wU1b[10];
#pragma unroll
    for (int m = 0; m < 10; m++) {
        int k0 = 2 * m * H3, k1 = (2 * m + 1) * H3;
        if (act) {
            wU0a[m] = pack2(U0[k0 + c1], U0[k1 + c1]);
            wU0b[m] = pack2(U0[k0 + c2], U0[k1 + c2]);
            wW1a[m] = pack2(W1[k0 + c1], W1[k1 + c1]);
            wW1b[m] = pack2(W1[k0 + c2], W1[k1 + c2]);
            wU1a[m] = pack2(U0 == U1 ? 0.f : U1[k0 + c1], U1[k1 + c1]);
            wU1a[m] = pack2(U1[k0 + c1], U1[k1 + c1]);
            wU1b[m] = pack2(U1[k0 + c2], U1[k1 + c2]);
        } else {
            wU0a[m] = wU0b[m] = wW1a[m] = wW1b[m] = wU1a[m] = wU1b[m] = 0ull;
        }
    }
    const u64 bU0a = pack2(b0r[c1], 0.f), bU0b = pack2(act ? b0r[c2] : 0.f, 0.f);
    const u64 bW1a = pack2(b1i[c1], 0.f), bW1b = pack2(act ? b1i[c2] : 0.f, 0.f);
    const u64 bU1a = pack2(b1r[c1], 0.f), bU1b = pack2(act ? b1r[c2] : 0.f, 0.f);

    // ---- state ----
    u64 hp0[10], hp1[10];
#pragma unroll
    for (int m = 0; m < 10; m++) { hp0[m] = 0ull; hp1[m] = 0ull; }
    float ho0 = 0.f, ho1 = 0.f;

    const int* xrow = x + b * TSTEPS;

    // software pipeline: xw pair for step t in regs, x index for t+1, prefetch chain
    int   xi1 = __ldg(xrow + 0);
    float2 xw = *reinterpret_cast<const float2*>(W0pad + xi1 * WPAD + 2 * lane);
    xi1 = __ldg(xrow + 1);

#pragma unroll 1
    for (int t = 0; t < TSTEPS; t++) {
        // prefetch xw for t+1 and x index for t+2
        float2 xwn = *reinterpret_cast<const float2*>(W0pad + xi1 * WPAD + 2 * lane);
        xi1 = __ldg(xrow + (t + 2 < TSTEPS ? t + 2 : TSTEPS - 1));

        // rec0 = h0@U0 + b0r ; rec1 = h1@U1 + b1r
        float r0a, r0b, r1a, r1b;
        matvec(wU0a, wU0b, bU0a, bU0b, hp0, r0a, r0b);
        matvec(wU1a, wU1b, bU1a, bU1b, hp1, r1a, r1b);

        // ---- layer 0 gate exchange + gating (unit i = lane, valid i<20) ----
        {
            float s1 = xw.x + r0a;                  // z-sum for i<20; r-sum on lanes 20-29
            float s2 = xw.y + r0b;                  // r-sum on lanes 0-9
            float ra = __shfl_sync(F, s1, 20 + lane);
            float rb = __shfl_sync(F, s2, lane - 10);
            float rr = (lane < 10) ? ra : rb;
            float xh = __shfl_sync(F, xw.y, 10 + lane);
            float rh = __shfl_sync(F, r0b, 10 + lane);
            float z  = sigm_fast(s1);
            float rg = sigm_fast(rr);
            float hh = tanh_fast(fmaf(rg, rh, xh));
            ho0 = z * (ho0 - hh) + hh;
        }
        // broadcast h0_new -> hp0 (k-pair packed)
#pragma unroll
        for (int m = 0; m < 10; m++) {
            float a = __shfl_sync(F, ho0, 2 * m);
            float c = __shfl_sync(F, ho0, 2 * m + 1);
            hp0[m] = pack2(a, c);
        }

        // xw1 = h0_new @ W1 + b1i
        float q1, q2;
        matvec(wW1a, wW1b, bW1a, bW1b, hp0, q1, q2);

        // ---- layer 1 gate exchange + gating ----
        {
            float s1 = q1 + r1a;
            float s2 = q2 + r1b;
            float ra = __shfl_sync(F, s1, 20 + lane);
            float rb = __shfl_sync(F, s2, lane - 10);
            float rr = (lane < 10) ? ra : rb;
            float xh = __shfl_sync(F, q2, 10 + lane);
            float rh = __shfl_sync(F, r1b, 10 + lane);
            float z  = sigm_fast(s1);
            float rg = sigm_fast(rr);
            float hh = tanh_fast(fmaf(rg, rh, xh));
            ho1 = z * (ho1 - hh) + hh;
        }
#pragma unroll
        for (int m = 0; m < 10; m++) {
            float a = __shfl_sync(F, ho1, 2 * m);
            float c = __shfl_sync(F, ho1, 2 * m + 1);
            hp1[m] = pack2(a, c);
        }

        xw = xwn;
    }

    // ---- logits = softmax(h1 @ Wd + bd) ; lane c<15 owns logit c ----
    float lg = -CUDART_INF_F;
    if (lane < LOUT) {
        lg = bd[lane];
#pragma unroll
        for (int m = 0; m < 10; m++) {
            float ha, hb;
            unp(hp1[m], ha, hb);
            lg = fmaf(ha, Wd[(2 * m) * LOUT + lane], lg);
            lg = fmaf(hb, Wd[(2 * m + 1) * LOUT + lane], lg);
        }
    }
    // reductions over the 16-lane group (lanes 0-15; lane 15 holds -inf)
    float mx = lg;
#pragma unroll
    for (int d = 8; d >= 1; d >>= 1) mx = fmaxf(mx, __shfl_xor_sync(F, mx, d));
    float p = __expf(lg - mx);
    float sm = p;
#pragma unroll
    for (int d = 8; d >= 1; d >>= 1) sm += __shfl_xor_sync(F, sm, d);
    if (lane < LOUT) out[b * LOUT + lane] = __fdividef(p, sm);
}

extern "C" void kernel_launch(void* const* d_in, const int* in_sizes, int n_in,
                              void* d_out, int out_size) {
    const int*   x   = (const int*)d_in[0];
    const float* W0  = (const float*)d_in[1];
    const float* U0  = (const float*)d_in[2];
    const float* b0i = (const float*)d_in[3];
    const float* b0r = (const float*)d_in[4];
    const float* W1  = (const float*)d_in[5];
    const float* U1  = (const float*)d_in[6];
    const float* b1i = (const float*)d_in[7];
    const float* b1r = (const float*)d_in[8];
    const float* Wd  = (const float*)d_in[9];
    const float* bd  = (const float*)d_in[10];
    // d_in[11] = drop_rate (identity), unused

    prep_w0<<<64, 256>>>(W0, b0i);
    gru2_kernel<<<NB / 4, 128>>>(x, U0, b0r, W1, U1, b1i, b1r, Wd, bd, (float*)d_out);
}